// round 4
// baseline (speedup 1.0000x reference)
#include <cuda_runtime.h>
#include <cstdint>
#include <math.h>

#define BB 64
#define TT 1380
#define XD 96
#define HD 192
#define CN 345

typedef unsigned long long ull;

// ---------------- scratch ----------------
static __device__ float g_M1[(size_t)BB * CN * XD];   // W2 @ X[b]
static __device__ float g_G [(size_t)BB * CN * HD];   // (M1 @ W1)*SCALE
static __device__ float g_S [(size_t)BB * CN * TT];   // logits
static __device__ float g_rmax[BB * CN];
static __device__ float g_rinv[BB * CN];

// ---------------- packed f32x2 helpers ----------------
__device__ __forceinline__ ull pk2(float x, float y) {
    ull r; asm("mov.b64 %0, {%1, %2};" : "=l"(r) : "f"(x), "f"(y)); return r;
}
__device__ __forceinline__ ull fma2(ull a, ull b, ull c) {
    ull d; asm("fma.rn.f32x2 %0, %1, %2, %3;" : "=l"(d) : "l"(a), "l"(b), "l"(c));
    return d;
}
__device__ __forceinline__ float2 upk(ull v) {
    float2 r; asm("mov.b64 {%0, %1}, %2;" : "=f"(r.x), "=f"(r.y) : "l"(v));
    return r;
}

constexpr int BM = 128, BK = 16;

// ---------------------------------------------------------------------------
// Packed-fp32 GEMM: C[b][m][n] = alpha * sum_k A[b][m][k] * Bop[k][n]
//   BTRANS=0: Bop[k][n] = Bsrc[n*ldb + k]   (e.g. A @ H^T)
//   BTRANS=1: Bop[k][n] = Bsrc[k*ldb + n]   (e.g. A @ W)
//   ASOFT=1 : A entries transformed exp(a - rmax[m]) * rinv[m] on load.
// CTA tile BM x BN x BK; NT = 16*(BN/8) threads; 8x8 microtile per thread
// with n vectorized into f32x2 pairs.
// ---------------------------------------------------------------------------
template <int BN, int NT, int BTRANS, int ASOFT>
__global__ void __launch_bounds__(NT, (NT == 256 ? 2 : 1)) gemm_f32x2(
    const float* __restrict__ A, const float* __restrict__ Bsrc, float* __restrict__ C,
    int M, int N, int K, int lda, int ldb, int ldc,
    long sA, long sB, long sC, float alpha,
    const float* __restrict__ rmaxA, const float* __restrict__ rinvA, int statStride)
{
    constexpr int TX = BN / 8;              // threads along n
    constexpr int A_F4 = (BM * BK) / 4;     // 512
    constexpr int B_F4 = (BN * BK) / 4;     // 512 or 768
    constexpr int AI = (A_F4 + NT - 1) / NT;
    constexpr int BI = (B_F4 + NT - 1) / NT;

    __shared__ float As[BK][BM + 8];
    __shared__ float Bs[BK][BN + 8];

    const int tid = threadIdx.x;
    const int tx = tid % TX;
    const int ty = tid / TX;
    const int b = blockIdx.z;

    A    += (long)b * sA;
    Bsrc += (long)b * sB;
    C    += (long)b * sC;
    const float* rmax = rmaxA + (long)b * statStride;
    const float* rinv = rinvA + (long)b * statStride;

    const int m0 = blockIdx.y * BM;
    const int n0 = blockIdx.x * BN;

    ull acc[8][4];
#pragma unroll
    for (int i = 0; i < 8; i++)
#pragma unroll
        for (int j = 0; j < 4; j++) acc[i][j] = 0ull;

    const int nb = (K + BK - 1) / BK;
    float4 pa[AI], pb[BI];

    auto loadA = [&](int kb) {
#pragma unroll
        for (int i = 0; i < AI; i++) {
            const int f = tid + i * NT;
            if (f < A_F4) {
                const int row = f >> 2, c4 = f & 3;
                const int gm = m0 + row, gk = kb * BK + c4 * 4;
                float4 v = make_float4(0.f, 0.f, 0.f, 0.f);
                if (gm < M && gk + 4 <= K)
                    v = *reinterpret_cast<const float4*>(A + (long)gm * lda + gk);
                pa[i] = v;
            }
        }
    };
    auto storeA = [&]() {
#pragma unroll
        for (int i = 0; i < AI; i++) {
            const int f = tid + i * NT;
            if (f < A_F4) {
                const int row = f >> 2, c4 = f & 3;
                float4 v = pa[i];
                if (ASOFT) {
                    const int gm = m0 + row;
                    if (gm < M) {
                        const float mx = rmax[gm], rv = rinv[gm];
                        v.x = __expf(v.x - mx) * rv;
                        v.y = __expf(v.y - mx) * rv;
                        v.z = __expf(v.z - mx) * rv;
                        v.w = __expf(v.w - mx) * rv;
                    } else {
                        v = make_float4(0.f, 0.f, 0.f, 0.f);
                    }
                }
                As[c4 * 4 + 0][row] = v.x;
                As[c4 * 4 + 1][row] = v.y;
                As[c4 * 4 + 2][row] = v.z;
                As[c4 * 4 + 3][row] = v.w;
            }
        }
    };
    auto loadB = [&](int kb) {
#pragma unroll
        for (int i = 0; i < BI; i++) {
            const int f = tid + i * NT;
            if (f < B_F4) {
                float4 v = make_float4(0.f, 0.f, 0.f, 0.f);
                if (BTRANS == 0) {
                    const int row = f >> 2, c4 = f & 3;
                    const int gn = n0 + row, gk = kb * BK + c4 * 4;
                    if (gn < N && gk + 4 <= K)
                        v = *reinterpret_cast<const float4*>(Bsrc + (long)gn * ldb + gk);
                } else {
                    const int kc = f / (BN / 4), n4 = f % (BN / 4);
                    const int gk = kb * BK + kc, gn = n0 + n4 * 4;
                    if (gk < K && gn + 4 <= N)
                        v = *reinterpret_cast<const float4*>(Bsrc + (long)gk * ldb + gn);
                }
                pb[i] = v;
            }
        }
    };
    auto storeB = [&]() {
#pragma unroll
        for (int i = 0; i < BI; i++) {
            const int f = tid + i * NT;
            if (f < B_F4) {
                const float4 v = pb[i];
                if (BTRANS == 0) {
                    const int row = f >> 2, c4 = f & 3;
                    Bs[c4 * 4 + 0][row] = v.x;
                    Bs[c4 * 4 + 1][row] = v.y;
                    Bs[c4 * 4 + 2][row] = v.z;
                    Bs[c4 * 4 + 3][row] = v.w;
                } else {
                    const int kc = f / (BN / 4), n4 = f % (BN / 4);
                    *reinterpret_cast<float4*>(&Bs[kc][n4 * 4]) = v;
                }
            }
        }
    };

    loadA(0); loadB(0);
    storeA(); storeB();
    __syncthreads();

    for (int kb = 0; kb < nb; kb++) {
        const bool more = (kb + 1 < nb);
        if (more) { loadA(kb + 1); loadB(kb + 1); }

#pragma unroll
        for (int kk = 0; kk < BK; kk++) {
            // a fragment: 8 m values (broadcast-packed)
            const float4 a0 = *reinterpret_cast<const float4*>(&As[kk][ty * 8]);
            const float4 a1 = *reinterpret_cast<const float4*>(&As[kk][ty * 8 + 4]);
            ull av[8];
            av[0] = pk2(a0.x, a0.x); av[1] = pk2(a0.y, a0.y);
            av[2] = pk2(a0.z, a0.z); av[3] = pk2(a0.w, a0.w);
            av[4] = pk2(a1.x, a1.x); av[5] = pk2(a1.y, a1.y);
            av[6] = pk2(a1.z, a1.z); av[7] = pk2(a1.w, a1.w);
            // b fragment: 8 n values as 4 packed pairs, straight from smem
            const ull* bp = reinterpret_cast<const ull*>(&Bs[kk][tx * 8]);
            const ull b0 = bp[0], b1 = bp[1], b2 = bp[2], b3 = bp[3];
#pragma unroll
            for (int i = 0; i < 8; i++) {
                acc[i][0] = fma2(av[i], b0, acc[i][0]);
                acc[i][1] = fma2(av[i], b1, acc[i][1]);
                acc[i][2] = fma2(av[i], b2, acc[i][2]);
                acc[i][3] = fma2(av[i], b3, acc[i][3]);
            }
        }

        __syncthreads();
        if (more) {
            storeA(); storeB();
            __syncthreads();
        }
    }

    // ---- epilogue ----
#pragma unroll
    for (int i = 0; i < 8; i++) {
        const int gm = m0 + ty * 8 + i;
        if (gm >= M) continue;
#pragma unroll
        for (int jg = 0; jg < 2; jg++) {
            const int gn = n0 + tx * 8 + jg * 4;
            if (gn + 4 <= N) {
                const float2 p0 = upk(acc[i][jg * 2 + 0]);
                const float2 p1 = upk(acc[i][jg * 2 + 1]);
                float4 v;
                v.x = p0.x * alpha; v.y = p0.y * alpha;
                v.z = p1.x * alpha; v.w = p1.y * alpha;
                *reinterpret_cast<float4*>(C + (long)gm * ldc + gn) = v;
            }
        }
    }
}

// ---------------------------------------------------------------------------
// Single-pass online softmax stats per row: rmax, 1/sum(exp(x-max))
// ---------------------------------------------------------------------------
__global__ void __launch_bounds__(128) softmax_stats(
    const float* __restrict__ S, float* __restrict__ rmax, float* __restrict__ rinv)
{
    const long row = blockIdx.x;
    const float4* p = reinterpret_cast<const float4*>(S + row * (long)TT);
    const int tid = threadIdx.x;

    float m = -3.0e38f, s = 0.f;
    for (int j = tid; j < TT / 4; j += 128) {
        const float4 v = p[j];
        const float mv = fmaxf(fmaxf(v.x, v.y), fmaxf(v.z, v.w));
        if (mv > m) { s *= __expf(m - mv); m = mv; }
        s += __expf(v.x - m) + __expf(v.y - m) + __expf(v.z - m) + __expf(v.w - m);
    }
#pragma unroll
    for (int o = 16; o; o >>= 1) {
        const float m2 = __shfl_xor_sync(0xffffffffu, m, o);
        const float s2 = __shfl_xor_sync(0xffffffffu, s, o);
        const float M = fmaxf(m, m2);
        s = s * __expf(m - M) + s2 * __expf(m2 - M);
        m = M;
    }
    __shared__ float sm[4], ss[4];
    if ((tid & 31) == 0) { sm[tid >> 5] = m; ss[tid >> 5] = s; }
    __syncthreads();
    if (tid == 0) {
        float M = sm[0];
#pragma unroll
        for (int i = 1; i < 4; i++) M = fmaxf(M, sm[i]);
        float S_ = 0.f;
#pragma unroll
        for (int i = 0; i < 4; i++) S_ += ss[i] * __expf(sm[i] - M);
        rmax[row] = M;
        rinv[row] = 1.0f / S_;
    }
}

// ---------------------------------------------------------------------------
extern "C" void kernel_launch(void* const* d_in, const int* in_sizes, int n_in,
                              void* d_out, int out_size)
{
    const float* X  = (const float*)d_in[0];   // [B,T,XD]
    const float* H  = (const float*)d_in[1];   // [B,T,HD]
    const float* W1 = (const float*)d_in[2];   // [XD,HD]
    const float* W2 = (const float*)d_in[3];   // [CN,T]
    float* out = (float*)d_out;                // [B,CN,HD]

    float *M1, *G, *S, *rmax, *rinv;
    cudaGetSymbolAddress((void**)&M1,   g_M1);
    cudaGetSymbolAddress((void**)&G,    g_G);
    cudaGetSymbolAddress((void**)&S,    g_S);
    cudaGetSymbolAddress((void**)&rmax, g_rmax);
    cudaGetSymbolAddress((void**)&rinv, g_rinv);

    const float SCALE = (float)(1.0 / (sqrt((double)XD) * sqrt((double)HD)));

    // K1: M1[b] = W2 @ X[b]           [CN,XD], K=T.  Bop[k][n]=X[k][n] -> TRANS
    gemm_f32x2<128, 256, 1, 0><<<dim3(1, 3, BB), 256>>>(
        W2, X, M1, CN, XD, TT, TT, XD, XD,
        0L, (long)TT * XD, (long)CN * XD, 1.0f, rmax, rinv, 0);

    // K2: G[b] = (M1[b] @ W1)*SCALE   [CN,HD], K=XD. Bop[k][n]=W1[k][n] -> TRANS
    gemm_f32x2<192, 384, 1, 0><<<dim3(1, 3, BB), 384>>>(
        M1, W1, G, CN, HD, XD, XD, HD, HD,
        (long)CN * XD, 0L, (long)CN * HD, SCALE, rmax, rinv, 0);

    // K3: S[b] = G[b] @ H[b]^T        [CN,T], K=HD.  Bop[k][n]=H[n][k] -> DIRECT
    gemm_f32x2<128, 256, 0, 0><<<dim3(11, 3, BB), 256>>>(
        G, H, S, CN, TT, HD, HD, HD, TT,
        (long)CN * HD, (long)TT * HD, (long)CN * TT, 1.0f, rmax, rinv, 0);

    // K4: online softmax stats
    softmax_stats<<<BB * CN, 128>>>(S, rmax, rinv);

    // K5: out[b] = softmax(S[b]) @ H[b]  [CN,HD], K=T. Bop[k][n]=H[k][n] -> TRANS
    gemm_f32x2<192, 384, 1, 1><<<dim3(1, 3, BB), 384>>>(
        S, H, out, CN, HD, TT, TT, HD, HD,
        (long)CN * TT, (long)TT * HD, (long)CN * HD, 1.0f, rmax, rinv, CN);
}

// round 5
// speedup vs baseline: 2.7310x; 2.7310x over previous
#include <cuda_runtime.h>
#include <cuda_fp16.h>
#include <cstdint>
#include <math.h>

#define BB 64
#define TT 1380
#define TTP 1384          // TT padded to 8 (16B fp16 chunks)
#define XD 96
#define HD 192
#define CN 345

// ---------------- fp32 scratch ----------------
static __device__ float g_M1[(size_t)BB * CN * XD];
static __device__ float g_G [(size_t)BB * CN * HD];
static __device__ float g_S [(size_t)BB * CN * TT];
static __device__ float g_rmax[BB * CN];
static __device__ float g_rinv[BB * CN];

// ---------------- fp16 hi/lo operand arrays ----------------
static __device__ __half g_W2h[(size_t)CN * TTP],          g_W2l[(size_t)CN * TTP];
static __device__ __half g_XTh[(size_t)BB * XD * TTP],     g_XTl[(size_t)BB * XD * TTP];
static __device__ __half g_Hh [(size_t)BB * TT * HD],      g_Hl [(size_t)BB * TT * HD];
static __device__ __half g_HTh[(size_t)BB * HD * TTP],     g_HTl[(size_t)BB * HD * TTP];
static __device__ __half g_W1Th[(size_t)HD * XD],          g_W1Tl[(size_t)HD * XD];
static __device__ __half g_M1h[(size_t)BB * CN * XD],      g_M1l[(size_t)BB * CN * XD];
static __device__ __half g_Gh [(size_t)BB * CN * HD],      g_Gl [(size_t)BB * CN * HD];
static __device__ __half g_Ph [(size_t)BB * CN * TTP],     g_Pl [(size_t)BB * CN * TTP];

// ---------------- PTX helpers ----------------
__device__ __forceinline__ uint32_t smem_u32(const void* p) {
    uint32_t a;
    asm("{ .reg .u64 t; cvta.to.shared.u64 t, %1; cvt.u32.u64 %0, t; }" : "=r"(a) : "l"(p));
    return a;
}
__device__ __forceinline__ void cpa(uint32_t dst, const void* src, int bytes) {
    asm volatile("cp.async.cg.shared.global [%0], [%1], 16, %2;"
                 :: "r"(dst), "l"(src), "r"(bytes) : "memory");
}
#define CP_COMMIT() asm volatile("cp.async.commit_group;" ::: "memory")
#define CP_WAIT1()  asm volatile("cp.async.wait_group 1;" ::: "memory")
#define CP_WAIT0()  asm volatile("cp.async.wait_group 0;" ::: "memory")

__device__ __forceinline__ void mma16(float* d, const uint32_t* a, uint32_t b0, uint32_t b1) {
    asm volatile(
        "mma.sync.aligned.m16n8k16.row.col.f32.f16.f16.f32 "
        "{%0,%1,%2,%3}, {%4,%5,%6,%7}, {%8,%9}, {%0,%1,%2,%3};"
        : "+f"(d[0]), "+f"(d[1]), "+f"(d[2]), "+f"(d[3])
        : "r"(a[0]), "r"(a[1]), "r"(a[2]), "r"(a[3]), "r"(b0), "r"(b1));
}

// smem geometry (fp16 units): 4 arrays of 128 rows x 40 per stage
#define ROWST 40
#define ARR_H 5120          // 128*40 fp16 per array
#define STAGE_H 20480       // 4 arrays
#define SMEM_BYTES (2 * STAGE_H * 2)   // 81920

// ---------------------------------------------------------------------------
// fp16 3-pass split GEMM: C[b][m][n] = alpha * sum_k A[m][k]*B[n][k]
// A (hi/lo): [*, lda] rows=m, k-contig.  B (hi/lo): [*, ldb] rows=n, k-contig.
// 128x128x32 tile, 256 threads, warps 2x4, cp.async double buffer.
// ---------------------------------------------------------------------------
__global__ void __launch_bounds__(256, 2) gemm_h3(
    const __half* __restrict__ Agh, const __half* __restrict__ Agl,
    const __half* __restrict__ Bgh, const __half* __restrict__ Bgl,
    float* __restrict__ C,
    int M, int N, int K, int lda, int ldb, int ldc,
    long sA, long sB, long sC, float alpha)
{
    extern __shared__ __half sm[];
    const uint32_t sb = smem_u32(sm);
    const int tid = threadIdx.x;
    const int wid = tid >> 5, lane = tid & 31;
    const int wm = wid >> 2, wn = wid & 3;
    const int grp = lane >> 2, qid = lane & 3;
    const int b = blockIdx.z;

    Agh += (long)b * sA; Agl += (long)b * sA;
    Bgh += (long)b * sB; Bgl += (long)b * sB;
    C   += (long)b * sC;

    const int m0 = blockIdx.y * 128;
    const int n0 = blockIdx.x * 128;

    int mtN = (M - m0 - wm * 64 + 15) >> 4;
    if (mtN < 0) mtN = 0; if (mtN > 4) mtN = 4;
    int ntN = (N - n0 - wn * 32 + 7) >> 3;
    if (ntN < 0) ntN = 0; if (ntN > 4) ntN = 4;

    float acc[4][4][4];
#pragma unroll
    for (int i = 0; i < 4; i++)
#pragma unroll
        for (int j = 0; j < 4; j++)
#pragma unroll
            for (int r = 0; r < 4; r++) acc[i][j][r] = 0.f;

    auto ldst = [&](int kb) {
        const uint32_t base = sb + (uint32_t)(kb & 1) * (STAGE_H * 2);
        const int k0 = kb * 32;
#pragma unroll
        for (int i = 0; i < 2; i++) {
            const int f = tid + i * 256;          // 0..511
            const int row = f >> 2, ch = f & 3;
            const int gk = k0 + ch * 8;
            int kbytes = (K - gk) * 2;
            if (kbytes > 16) kbytes = 16;
            if (kbytes < 0) kbytes = 0;
            const uint32_t doff = (uint32_t)(row * ROWST + ch * 8) * 2;
            // A
            {
                const int gm = m0 + row;
                const int bytes = (gm < M) ? kbytes : 0;
                const long off = bytes ? ((long)gm * lda + gk) : 0;
                cpa(base + 0 * (ARR_H * 2) + doff, Agh + off, bytes);
                cpa(base + 1 * (ARR_H * 2) + doff, Agl + off, bytes);
            }
            // B
            {
                const int gn = n0 + row;
                const int bytes = (gn < N) ? kbytes : 0;
                const long off = bytes ? ((long)gn * ldb + gk) : 0;
                cpa(base + 2 * (ARR_H * 2) + doff, Bgh + off, bytes);
                cpa(base + 3 * (ARR_H * 2) + doff, Bgl + off, bytes);
            }
        }
    };

    const int nb = (K + 31) >> 5;
    ldst(0); CP_COMMIT();

    for (int kb = 0; kb < nb; kb++) {
        if (kb + 1 < nb) { ldst(kb + 1); CP_COMMIT(); CP_WAIT1(); }
        else             { CP_WAIT0(); }
        __syncthreads();

        const __half* Ash = sm + (kb & 1) * STAGE_H;
        const __half* Asl = Ash + ARR_H;
        const __half* Bsh = Ash + 2 * ARR_H;
        const __half* Bsl = Ash + 3 * ARR_H;

#pragma unroll
        for (int kc = 0; kc < 2; kc++) {
            const int kf = kc * 16;
            uint32_t ah[4][4], al[4][4];
#pragma unroll
            for (int mt = 0; mt < 4; mt++) {
                if (mt < mtN) {
                    const int r0 = wm * 64 + mt * 16 + grp;
                    ah[mt][0] = *(const uint32_t*)(Ash + (r0    ) * ROWST + kf     + 2 * qid);
                    ah[mt][1] = *(const uint32_t*)(Ash + (r0 + 8) * ROWST + kf     + 2 * qid);
                    ah[mt][2] = *(const uint32_t*)(Ash + (r0    ) * ROWST + kf + 8 + 2 * qid);
                    ah[mt][3] = *(const uint32_t*)(Ash + (r0 + 8) * ROWST + kf + 8 + 2 * qid);
                    al[mt][0] = *(const uint32_t*)(Asl + (r0    ) * ROWST + kf     + 2 * qid);
                    al[mt][1] = *(const uint32_t*)(Asl + (r0 + 8) * ROWST + kf     + 2 * qid);
                    al[mt][2] = *(const uint32_t*)(Asl + (r0    ) * ROWST + kf + 8 + 2 * qid);
                    al[mt][3] = *(const uint32_t*)(Asl + (r0 + 8) * ROWST + kf + 8 + 2 * qid);
                }
            }
#pragma unroll
            for (int nt = 0; nt < 4; nt++) {
                if (nt < ntN) {
                    const int c0 = wn * 32 + nt * 8 + grp;
                    const uint32_t bh0 = *(const uint32_t*)(Bsh + c0 * ROWST + kf     + 2 * qid);
                    const uint32_t bh1 = *(const uint32_t*)(Bsh + c0 * ROWST + kf + 8 + 2 * qid);
                    const uint32_t bl0 = *(const uint32_t*)(Bsl + c0 * ROWST + kf     + 2 * qid);
                    const uint32_t bl1 = *(const uint32_t*)(Bsl + c0 * ROWST + kf + 8 + 2 * qid);
#pragma unroll
                    for (int mt = 0; mt < 4; mt++) {
                        if (mt < mtN) {
                            mma16(acc[mt][nt], ah[mt], bh0, bh1);
                            mma16(acc[mt][nt], ah[mt], bl0, bl1);
                            mma16(acc[mt][nt], al[mt], bh0, bh1);
                        }
                    }
                }
            }
        }
        __syncthreads();
    }

    // epilogue
#pragma unroll
    for (int mt = 0; mt < 4; mt++) {
        if (mt >= mtN) break;
#pragma unroll
        for (int nt = 0; nt < 4; nt++) {
            if (nt >= ntN) break;
            const int gm = m0 + wm * 64 + mt * 16 + grp;
            const int gn = n0 + wn * 32 + nt * 8 + 2 * qid;
            if (gn + 2 <= N) {
                if (gm < M) {
                    float2 v = make_float2(acc[mt][nt][0] * alpha, acc[mt][nt][1] * alpha);
                    *reinterpret_cast<float2*>(C + (long)gm * ldc + gn) = v;
                }
                if (gm + 8 < M) {
                    float2 v = make_float2(acc[mt][nt][2] * alpha, acc[mt][nt][3] * alpha);
                    *reinterpret_cast<float2*>(C + (long)(gm + 8) * ldc + gn) = v;
                }
            }
        }
    }
}

// ---------------------------------------------------------------------------
// conversion kernels
// ---------------------------------------------------------------------------
__global__ void split_plain(const float* __restrict__ in,
                            __half* __restrict__ oh, __half* __restrict__ ol, long n2)
{
    const long i = (long)blockIdx.x * blockDim.x + threadIdx.x;
    if (i < n2) {
        const float2 v = reinterpret_cast<const float2*>(in)[i];
        const __half hx = __float2half(v.x), hy = __float2half(v.y);
        const __half lx = __float2half(v.x - __half2float(hx));
        const __half ly = __float2half(v.y - __half2float(hy));
        reinterpret_cast<__half2*>(oh)[i] = __halves2half2(hx, hy);
        reinterpret_cast<__half2*>(ol)[i] = __halves2half2(lx, ly);
    }
}

// rows x cols fp32 -> padded-ld fp16 hi/lo (same orientation)
__global__ void split_rows(const float* __restrict__ in,
                           __half* __restrict__ oh, __half* __restrict__ ol,
                           int rows, int cols, int ldo)
{
    const int c4n = cols / 4;
    const long f = (long)blockIdx.x * blockDim.x + threadIdx.x;
    if (f < (long)rows * c4n) {
        const int row = (int)(f / c4n), c4 = (int)(f % c4n);
        const float4 v = *reinterpret_cast<const float4*>(in + (long)row * cols + c4 * 4);
        __half h0 = __float2half(v.x), h1 = __float2half(v.y);
        __half h2 = __float2half(v.z), h3 = __float2half(v.w);
        __half l0 = __float2half(v.x - __half2float(h0));
        __half l1 = __float2half(v.y - __half2float(h1));
        __half l2 = __float2half(v.z - __half2float(h2));
        __half l3 = __float2half(v.w - __half2float(h3));
        __half2* ph = reinterpret_cast<__half2*>(oh + (long)row * ldo + c4 * 4);
        __half2* pl = reinterpret_cast<__half2*>(ol + (long)row * ldo + c4 * 4);
        ph[0] = __halves2half2(h0, h1); ph[1] = __halves2half2(h2, h3);
        pl[0] = __halves2half2(l0, l1); pl[1] = __halves2half2(l2, l3);
    }
}

// in [R][Cc] fp32 -> out [Cc][ldo] fp16 hi/lo (transposed), batched
__global__ void split_transpose(const float* __restrict__ in,
                                __half* __restrict__ oh, __half* __restrict__ ol,
                                int R, int Cc, int ldo, long sIn, long sOut)
{
    __shared__ float t[32][33];
    const int b = blockIdx.z;
    in += (long)b * sIn; oh += (long)b * sOut; ol += (long)b * sOut;
    const int c0 = blockIdx.x * 32, r0 = blockIdx.y * 32;
#pragma unroll
    for (int i = 0; i < 4; i++) {
        const int r = r0 + threadIdx.y + 8 * i, c = c0 + threadIdx.x;
        t[threadIdx.y + 8 * i][threadIdx.x] =
            (r < R && c < Cc) ? in[(long)r * Cc + c] : 0.f;
    }
    __syncthreads();
#pragma unroll
    for (int i = 0; i < 4; i++) {
        const int c = c0 + threadIdx.y + 8 * i, r = r0 + threadIdx.x;
        if (c < Cc && r < R) {
            const float v = t[threadIdx.x][threadIdx.y + 8 * i];
            const __half h = __float2half(v);
            oh[(long)c * ldo + r] = h;
            ol[(long)c * ldo + r] = __float2half(v - __half2float(h));
        }
    }
}

// P = exp(S - rmax)*rinv, split to fp16 hi/lo with padded ld
__global__ void __launch_bounds__(128) split_softmax(
    const float* __restrict__ S, const float* __restrict__ rmax,
    const float* __restrict__ rinv, __half* __restrict__ oh, __half* __restrict__ ol)
{
    const long row = blockIdx.x;
    const float4* p = reinterpret_cast<const float4*>(S + row * (long)TT);
    const float mx = rmax[row], rv = rinv[row];
    for (int j = threadIdx.x; j < TT / 4; j += 128) {
        const float4 v = p[j];
        float f0 = __expf(v.x - mx) * rv, f1 = __expf(v.y - mx) * rv;
        float f2 = __expf(v.z - mx) * rv, f3 = __expf(v.w - mx) * rv;
        __half h0 = __float2half(f0), h1 = __float2half(f1);
        __half h2 = __float2half(f2), h3 = __float2half(f3);
        __half l0 = __float2half(f0 - __half2float(h0));
        __half l1 = __float2half(f1 - __half2float(h1));
        __half l2 = __float2half(f2 - __half2float(h2));
        __half l3 = __float2half(f3 - __half2float(h3));
        __half2* ph = reinterpret_cast<__half2*>(oh + row * (long)TTP + j * 4);
        __half2* pl = reinterpret_cast<__half2*>(ol + row * (long)TTP + j * 4);
        ph[0] = __halves2half2(h0, h1); ph[1] = __halves2half2(h2, h3);
        pl[0] = __halves2half2(l0, l1); pl[1] = __halves2half2(l2, l3);
    }
}

// per-row softmax stats (online)
__global__ void __launch_bounds__(128) softmax_stats(
    const float* __restrict__ S, float* __restrict__ rmax, float* __restrict__ rinv)
{
    const long row = blockIdx.x;
    const float4* p = reinterpret_cast<const float4*>(S + row * (long)TT);
    const int tid = threadIdx.x;
    float m = -3.0e38f, s = 0.f;
    for (int j = tid; j < TT / 4; j += 128) {
        const float4 v = p[j];
        const float mv = fmaxf(fmaxf(v.x, v.y), fmaxf(v.z, v.w));
        if (mv > m) { s *= __expf(m - mv); m = mv; }
        s += __expf(v.x - m) + __expf(v.y - m) + __expf(v.z - m) + __expf(v.w - m);
    }
#pragma unroll
    for (int o = 16; o; o >>= 1) {
        const float m2 = __shfl_xor_sync(0xffffffffu, m, o);
        const float s2 = __shfl_xor_sync(0xffffffffu, s, o);
        const float M = fmaxf(m, m2);
        s = s * __expf(m - M) + s2 * __expf(m2 - M);
        m = M;
    }
    __shared__ float sm[4], ss[4];
    if ((tid & 31) == 0) { sm[tid >> 5] = m; ss[tid >> 5] = s; }
    __syncthreads();
    if (tid == 0) {
        float M = sm[0];
#pragma unroll
        for (int i = 1; i < 4; i++) M = fmaxf(M, sm[i]);
        float S_ = 0.f;
#pragma unroll
        for (int i = 0; i < 4; i++) S_ += ss[i] * __expf(sm[i] - M);
        rmax[row] = M;
        rinv[row] = 1.0f / S_;
    }
}

// ---------------------------------------------------------------------------
extern "C" void kernel_launch(void* const* d_in, const int* in_sizes, int n_in,
                              void* d_out, int out_size)
{
    const float* X  = (const float*)d_in[0];   // [B,T,XD]
    const float* H  = (const float*)d_in[1];   // [B,T,HD]
    const float* W1 = (const float*)d_in[2];   // [XD,HD]
    const float* W2 = (const float*)d_in[3];   // [CN,T]
    float* out = (float*)d_out;                // [B,CN,HD]

    float *M1, *G, *S, *rmax, *rinv;
    cudaGetSymbolAddress((void**)&M1,   g_M1);
    cudaGetSymbolAddress((void**)&G,    g_G);
    cudaGetSymbolAddress((void**)&S,    g_S);
    cudaGetSymbolAddress((void**)&rmax, g_rmax);
    cudaGetSymbolAddress((void**)&rinv, g_rinv);

    __half *W2h, *W2l, *XTh, *XTl, *Hh, *Hl, *HTh, *HTl, *W1Th, *W1Tl;
    __half *M1h, *M1l, *Gh, *Gl, *Ph, *Pl;
    cudaGetSymbolAddress((void**)&W2h, g_W2h);   cudaGetSymbolAddress((void**)&W2l, g_W2l);
    cudaGetSymbolAddress((void**)&XTh, g_XTh);   cudaGetSymbolAddress((void**)&XTl, g_XTl);
    cudaGetSymbolAddress((void**)&Hh,  g_Hh);    cudaGetSymbolAddress((void**)&Hl,  g_Hl);
    cudaGetSymbolAddress((void**)&HTh, g_HTh);   cudaGetSymbolAddress((void**)&HTl, g_HTl);
    cudaGetSymbolAddress((void**)&W1Th, g_W1Th); cudaGetSymbolAddress((void**)&W1Tl, g_W1Tl);
    cudaGetSymbolAddress((void**)&M1h, g_M1h);   cudaGetSymbolAddress((void**)&M1l, g_M1l);
    cudaGetSymbolAddress((void**)&Gh,  g_Gh);    cudaGetSymbolAddress((void**)&Gl,  g_Gl);
    cudaGetSymbolAddress((void**)&Ph,  g_Ph);    cudaGetSymbolAddress((void**)&Pl,  g_Pl);

    cudaFuncSetAttribute(gemm_h3, cudaFuncAttributeMaxDynamicSharedMemorySize, SMEM_BYTES);

    const float SCALE = (float)(1.0 / (sqrt((double)XD) * sqrt((double)HD)));

    // --- input conversions ---
    // W2 [CN,TT] -> padded rows
    {
        const long f = (long)CN * (TT / 4);
        split_rows<<<(unsigned)((f + 255) / 256), 256>>>(W2, W2h, W2l, CN, TT, TTP);
    }
    // X [B][T][XD] -> XT [B][XD][TTP]
    split_transpose<<<dim3((XD + 31) / 32, (TT + 31) / 32, BB), dim3(32, 8)>>>(
        X, XTh, XTl, TT, XD, TTP, (long)TT * XD, (long)XD * TTP);
    // H plain [B][T][HD]
    {
        const long n2 = (long)BB * TT * HD / 2;
        split_plain<<<(unsigned)((n2 + 255) / 256), 256>>>(H, Hh, Hl, n2);
    }
    // H -> HT [B][HD][TTP]
    split_transpose<<<dim3((HD + 31) / 32, (TT + 31) / 32, BB), dim3(32, 8)>>>(
        H, HTh, HTl, TT, HD, TTP, (long)TT * HD, (long)HD * TTP);
    // W1 [XD][HD] -> W1T [HD][XD]
    split_transpose<<<dim3((HD + 31) / 32, (XD + 31) / 32, 1), dim3(32, 8)>>>(
        W1, W1Th, W1Tl, XD, HD, XD, 0L, 0L);

    // K1: M1[b] = W2 @ X[b]   [CN,XD], K=TT
    gemm_h3<<<dim3(1, 3, BB), 256, SMEM_BYTES>>>(
        W2h, W2l, XTh, XTl, M1, CN, XD, TT, TTP, TTP, XD,
        0L, (long)XD * TTP, (long)CN * XD, 1.0f);

    // convert M1
    {
        const long n2 = (long)BB * CN * XD / 2;
        split_plain<<<(unsigned)((n2 + 255) / 256), 256>>>(M1, M1h, M1l, n2);
    }

    // K2: G[b] = (M1[b] @ W1) * SCALE   [CN,HD], K=XD
    gemm_h3<<<dim3(2, 3, BB), 256, SMEM_BYTES>>>(
        M1h, M1l, W1Th, W1Tl, G, CN, HD, XD, XD, XD, HD,
        (long)CN * XD, 0L, (long)CN * HD, SCALE);

    // convert G
    {
        const long n2 = (long)BB * CN * HD / 2;
        split_plain<<<(unsigned)((n2 + 255) / 256), 256>>>(G, Gh, Gl, n2);
    }

    // K3: S[b] = G[b] @ H[b]^T   [CN,TT], K=HD
    gemm_h3<<<dim3(11, 3, BB), 256, SMEM_BYTES>>>(
        Gh, Gl, Hh, Hl, S, CN, TT, HD, HD, HD, TT,
        (long)CN * HD, (long)TT * HD, (long)CN * TT, 1.0f);

    // K4: softmax stats + P split
    softmax_stats<<<BB * CN, 128>>>(S, rmax, rinv);
    split_softmax<<<BB * CN, 128>>>(S, rmax, rinv, Ph, Pl);

    // K5: out[b] = P[b] @ H[b]   [CN,HD], K=TT
    gemm_h3<<<dim3(2, 3, BB), 256, SMEM_BYTES>>>(
        Ph, Pl, HTh, HTl, out, CN, HD, TT, TTP, TTP, HD,
        (long)CN * TTP, (long)HD * TTP, (long)CN * HD, 1.0f);
}

// round 6
// speedup vs baseline: 3.0357x; 1.1116x over previous
#include <cuda_runtime.h>
#include <cuda_fp16.h>
#include <cstdint>
#include <math.h>

#define BB 64
#define TT 1380
#define TTP 1384
#define XD 96
#define HD 192
#define CN 345

// ---------------- scratch ----------------
static __device__ float g_S [(size_t)BB * CN * TT];
static __device__ __half g_W2h[(size_t)CN * TTP],        g_W2l[(size_t)CN * TTP];
static __device__ __half g_XTh[(size_t)BB * XD * TTP],   g_XTl[(size_t)BB * XD * TTP];
static __device__ __half g_Hh [(size_t)BB * TT * HD],    g_Hl [(size_t)BB * TT * HD];
static __device__ __half g_HTh[(size_t)BB * HD * TTP],   g_HTl[(size_t)BB * HD * TTP];
static __device__ __half g_W1Th[(size_t)HD * XD],        g_W1Tl[(size_t)HD * XD];
static __device__ __half g_M1h[(size_t)BB * CN * XD],    g_M1l[(size_t)BB * CN * XD];
static __device__ __half g_Gh [(size_t)BB * CN * HD],    g_Gl [(size_t)BB * CN * HD];
static __device__ __half g_Ph [(size_t)BB * CN * TTP],   g_Pl [(size_t)BB * CN * TTP];

// ---------------- PTX helpers ----------------
__device__ __forceinline__ uint32_t smem_u32(const void* p) {
    uint32_t a;
    asm("{ .reg .u64 t; cvta.to.shared.u64 t, %1; cvt.u32.u64 %0, t; }" : "=r"(a) : "l"(p));
    return a;
}
__device__ __forceinline__ void cpa(uint32_t dst, const void* src, int bytes) {
    asm volatile("cp.async.cg.shared.global [%0], [%1], 16, %2;"
                 :: "r"(dst), "l"(src), "r"(bytes) : "memory");
}
#define CP_COMMIT() asm volatile("cp.async.commit_group;" ::: "memory")
#define CP_WAIT1()  asm volatile("cp.async.wait_group 1;" ::: "memory")
#define CP_WAIT0()  asm volatile("cp.async.wait_group 0;" ::: "memory")

__device__ __forceinline__ void mma16(float* d, const uint32_t* a, uint32_t b0, uint32_t b1) {
    asm volatile(
        "mma.sync.aligned.m16n8k16.row.col.f32.f16.f16.f32 "
        "{%0,%1,%2,%3}, {%4,%5,%6,%7}, {%8,%9}, {%0,%1,%2,%3};"
        : "+f"(d[0]), "+f"(d[1]), "+f"(d[2]), "+f"(d[3])
        : "r"(a[0]), "r"(a[1]), "r"(a[2]), "r"(a[3]), "r"(b0), "r"(b1));
}
__device__ __forceinline__ __half2 split_hi(float x, float y, __half2& lo) {
    const __half hx = __float2half(x), hy = __float2half(y);
    lo = __halves2half2(__float2half(x - __half2float(hx)),
                        __float2half(y - __half2float(hy)));
    return __halves2half2(hx, hy);
}

#define ROWST 40
#define ARR_H 5120
#define STAGE_H 20480
#define SMEM_BYTES (2 * STAGE_H * 2)

// ---------------------------------------------------------------------------
// fp16 3-pass split GEMM: C[m][n] = alpha * sum_k A[m][k]*B[n][k]
// OUT=0: fp32 to Cf (ldc).  OUT=1: fp16 hi/lo to Ch/Cl (ldc).
// OUT=2: fp16 hi/lo scattered: n -> (b1=n/XD, x=n%XD), addr b1*sC + m*XD + x.
// ---------------------------------------------------------------------------
template <int OUT>
__global__ void __launch_bounds__(256, 2) gemm_h3(
    const __half* __restrict__ Agh, const __half* __restrict__ Agl,
    const __half* __restrict__ Bgh, const __half* __restrict__ Bgl,
    float* __restrict__ Cf, __half* __restrict__ Ch, __half* __restrict__ Cl,
    int M, int N, int K, int lda, int ldb, int ldc,
    long sA, long sB, long sC, float alpha)
{
    extern __shared__ __half sm[];
    const uint32_t sb = smem_u32(sm);
    const int tid = threadIdx.x;
    const int wid = tid >> 5, lane = tid & 31;
    const int wm = wid >> 2, wn = wid & 3;
    const int grp = lane >> 2, qid = lane & 3;
    const int b = blockIdx.z;

    Agh += (long)b * sA; Agl += (long)b * sA;
    Bgh += (long)b * sB; Bgl += (long)b * sB;
    if (OUT == 0) Cf += (long)b * sC;

    const int m0 = blockIdx.y * 128;
    const int n0 = blockIdx.x * 128;

    int mtN = (M - m0 - wm * 64 + 15) >> 4;
    if (mtN < 0) mtN = 0; if (mtN > 4) mtN = 4;
    int ntN = (N - n0 - wn * 32 + 7) >> 3;
    if (ntN < 0) ntN = 0; if (ntN > 4) ntN = 4;

    float acc[4][4][4];
#pragma unroll
    for (int i = 0; i < 4; i++)
#pragma unroll
        for (int j = 0; j < 4; j++)
#pragma unroll
            for (int r = 0; r < 4; r++) acc[i][j][r] = 0.f;

    auto ldst = [&](int kb) {
        const uint32_t base = sb + (uint32_t)(kb & 1) * (STAGE_H * 2);
        const int k0 = kb * 32;
#pragma unroll
        for (int i = 0; i < 2; i++) {
            const int f = tid + i * 256;
            const int row = f >> 2, ch = f & 3;
            const int gk = k0 + ch * 8;
            int kbytes = (K - gk) * 2;
            if (kbytes > 16) kbytes = 16;
            if (kbytes < 0) kbytes = 0;
            const uint32_t doff = (uint32_t)(row * ROWST + ch * 8) * 2;
            {
                const int gm = m0 + row;
                const int bytes = (gm < M) ? kbytes : 0;
                const long off = bytes ? ((long)gm * lda + gk) : 0;
                cpa(base + 0 * (ARR_H * 2) + doff, Agh + off, bytes);
                cpa(base + 1 * (ARR_H * 2) + doff, Agl + off, bytes);
            }
            {
                const int gn = n0 + row;
                const int bytes = (gn < N) ? kbytes : 0;
                const long off = bytes ? ((long)gn * ldb + gk) : 0;
                cpa(base + 2 * (ARR_H * 2) + doff, Bgh + off, bytes);
                cpa(base + 3 * (ARR_H * 2) + doff, Bgl + off, bytes);
            }
        }
    };

    const int nb = (K + 31) >> 5;
    ldst(0); CP_COMMIT();

    for (int kb = 0; kb < nb; kb++) {
        if (kb + 1 < nb) { ldst(kb + 1); CP_COMMIT(); CP_WAIT1(); }
        else             { CP_WAIT0(); }
        __syncthreads();

        const __half* Ash = sm + (kb & 1) * STAGE_H;
        const __half* Asl = Ash + ARR_H;
        const __half* Bsh = Ash + 2 * ARR_H;
        const __half* Bsl = Ash + 3 * ARR_H;

#pragma unroll
        for (int kc = 0; kc < 2; kc++) {
            const int kf = kc * 16;
            uint32_t ah[4][4], al[4][4];
#pragma unroll
            for (int mt = 0; mt < 4; mt++) {
                if (mt < mtN) {
                    const int r0 = wm * 64 + mt * 16 + grp;
                    ah[mt][0] = *(const uint32_t*)(Ash + (r0    ) * ROWST + kf     + 2 * qid);
                    ah[mt][1] = *(const uint32_t*)(Ash + (r0 + 8) * ROWST + kf     + 2 * qid);
                    ah[mt][2] = *(const uint32_t*)(Ash + (r0    ) * ROWST + kf + 8 + 2 * qid);
                    ah[mt][3] = *(const uint32_t*)(Ash + (r0 + 8) * ROWST + kf + 8 + 2 * qid);
                    al[mt][0] = *(const uint32_t*)(Asl + (r0    ) * ROWST + kf     + 2 * qid);
                    al[mt][1] = *(const uint32_t*)(Asl + (r0 + 8) * ROWST + kf     + 2 * qid);
                    al[mt][2] = *(const uint32_t*)(Asl + (r0    ) * ROWST + kf + 8 + 2 * qid);
                    al[mt][3] = *(const uint32_t*)(Asl + (r0 + 8) * ROWST + kf + 8 + 2 * qid);
                }
            }
#pragma unroll
            for (int nt = 0; nt < 4; nt++) {
                if (nt < ntN) {
                    const int c0 = wn * 32 + nt * 8 + grp;
                    const uint32_t bh0 = *(const uint32_t*)(Bsh + c0 * ROWST + kf     + 2 * qid);
                    const uint32_t bh1 = *(const uint32_t*)(Bsh + c0 * ROWST + kf + 8 + 2 * qid);
                    const uint32_t bl0 = *(const uint32_t*)(Bsl + c0 * ROWST + kf     + 2 * qid);
                    const uint32_t bl1 = *(const uint32_t*)(Bsl + c0 * ROWST + kf + 8 + 2 * qid);
#pragma unroll
                    for (int mt = 0; mt < 4; mt++) {
                        if (mt < mtN) {
                            mma16(acc[mt][nt], ah[mt], bh0, bh1);
                            mma16(acc[mt][nt], ah[mt], bl0, bl1);
                            mma16(acc[mt][nt], al[mt], bh0, bh1);
                        }
                    }
                }
            }
        }
        __syncthreads();
    }

    // ---- epilogue ----
#pragma unroll
    for (int mt = 0; mt < 4; mt++) {
        if (mt >= mtN) break;
#pragma unroll
        for (int nt = 0; nt < 4; nt++) {
            if (nt >= ntN) break;
            const int gmA = m0 + wm * 64 + mt * 16 + grp;
            const int gn  = n0 + wn * 32 + nt * 8 + 2 * qid;
            if (gn + 2 > N) continue;
#pragma unroll
            for (int half_ = 0; half_ < 2; half_++) {
                const int gm = gmA + half_ * 8;
                if (gm >= M) continue;
                const float v0 = acc[mt][nt][half_ * 2 + 0] * alpha;
                const float v1 = acc[mt][nt][half_ * 2 + 1] * alpha;
                if (OUT == 0) {
                    *reinterpret_cast<float2*>(Cf + (long)gm * ldc + gn) =
                        make_float2(v0, v1);
                } else if (OUT == 1) {
                    __half2 lo, hi = split_hi(v0, v1, lo);
                    *reinterpret_cast<__half2*>(Ch + (long)gm * ldc + gn) = hi;
                    *reinterpret_cast<__half2*>(Cl + (long)gm * ldc + gn) = lo;
                } else {
                    const int b1 = gn / XD, x = gn - b1 * XD;
                    const long addr = (long)b1 * sC + (long)gm * XD + x;
                    __half2 lo, hi = split_hi(v0, v1, lo);
                    *reinterpret_cast<__half2*>(Ch + addr) = hi;
                    *reinterpret_cast<__half2*>(Cl + addr) = lo;
                }
            }
        }
    }
}

// ---------------------------------------------------------------------------
// conversions
// ---------------------------------------------------------------------------
__global__ void split_rows(const float* __restrict__ in,
                           __half* __restrict__ oh, __half* __restrict__ ol,
                           int rows, int cols, int ldo)
{
    const int c4n = cols / 4;
    const long f = (long)blockIdx.x * blockDim.x + threadIdx.x;
    if (f < (long)rows * c4n) {
        const int row = (int)(f / c4n), c4 = (int)(f % c4n);
        const float4 v = *reinterpret_cast<const float4*>(in + (long)row * cols + c4 * 4);
        __half2 l0, h0 = split_hi(v.x, v.y, l0);
        __half2 l1, h1 = split_hi(v.z, v.w, l1);
        __half2* ph = reinterpret_cast<__half2*>(oh + (long)row * ldo + c4 * 4);
        __half2* pl = reinterpret_cast<__half2*>(ol + (long)row * ldo + c4 * 4);
        ph[0] = h0; ph[1] = h1;
        pl[0] = l0; pl[1] = l1;
    }
}

__global__ void split_transpose(const float* __restrict__ in,
                                __half* __restrict__ oh, __half* __restrict__ ol,
                                int R, int Cc, int ldo, long sIn, long sOut)
{
    __shared__ float t[32][33];
    const int b = blockIdx.z;
    in += (long)b * sIn; oh += (long)b * sOut; ol += (long)b * sOut;
    const int c0 = blockIdx.x * 32, r0 = blockIdx.y * 32;
#pragma unroll
    for (int i = 0; i < 4; i++) {
        const int r = r0 + threadIdx.y + 8 * i, c = c0 + threadIdx.x;
        t[threadIdx.y + 8 * i][threadIdx.x] =
            (r < R && c < Cc) ? in[(long)r * Cc + c] : 0.f;
    }
    __syncthreads();
#pragma unroll
    for (int i = 0; i < 4; i++) {
        const int c = c0 + threadIdx.y + 8 * i, r = r0 + threadIdx.x;
        if (c < Cc && r < R) {
            const float v = t[threadIdx.x][threadIdx.y + 8 * i];
            const __half h = __float2half(v);
            oh[(long)c * ldo + r] = h;
            ol[(long)c * ldo + r] = __float2half(v - __half2float(h));
        }
    }
}

// H: one read -> plain Hh/Hl [b][t][h] + transposed HTh/HTl [b][h][TTP]
__global__ void conv_H(const float* __restrict__ H,
                       __half* __restrict__ Hh, __half* __restrict__ Hl,
                       __half* __restrict__ HTh, __half* __restrict__ HTl)
{
    __shared__ float t[32][33];
    const int b = blockIdx.z;
    const float* in = H + (long)b * TT * HD;
    const int c0 = blockIdx.x * 32, r0 = blockIdx.y * 32;
#pragma unroll
    for (int i = 0; i < 4; i++) {
        const int r = r0 + threadIdx.y + 8 * i, c = c0 + threadIdx.x;
        float v = 0.f;
        if (r < TT) {
            v = in[(long)r * HD + c];
            const __half h = __float2half(v);
            Hh[(long)b * TT * HD + (long)r * HD + c] = h;
            Hl[(long)b * TT * HD + (long)r * HD + c] =
                __float2half(v - __half2float(h));
        }
        t[threadIdx.y + 8 * i][threadIdx.x] = v;
    }
    __syncthreads();
#pragma unroll
    for (int i = 0; i < 4; i++) {
        const int c = c0 + threadIdx.y + 8 * i, r = r0 + threadIdx.x;
        if (r < TT) {
            const float v = t[threadIdx.x][threadIdx.y + 8 * i];
            const __half h = __float2half(v);
            HTh[(long)b * HD * TTP + (long)c * TTP + r] = h;
            HTl[(long)b * HD * TTP + (long)c * TTP + r] =
                __float2half(v - __half2float(h));
        }
    }
}

// fused: row stats (online max/sum) + P = exp(S-m)*rinv split to fp16 hi/lo
__global__ void __launch_bounds__(128) softmax_fused(
    const float* __restrict__ S, __half* __restrict__ oh, __half* __restrict__ ol)
{
    const long row = blockIdx.x;
    const float4* p = reinterpret_cast<const float4*>(S + row * (long)TT);
    const int tid = threadIdx.x;

    float m = -3.0e38f, s = 0.f;
    for (int j = tid; j < TT / 4; j += 128) {
        const float4 v = p[j];
        const float mv = fmaxf(fmaxf(v.x, v.y), fmaxf(v.z, v.w));
        if (mv > m) { s *= __expf(m - mv); m = mv; }
        s += __expf(v.x - m) + __expf(v.y - m) + __expf(v.z - m) + __expf(v.w - m);
    }
#pragma unroll
    for (int o = 16; o; o >>= 1) {
        const float m2 = __shfl_xor_sync(0xffffffffu, m, o);
        const float s2 = __shfl_xor_sync(0xffffffffu, s, o);
        const float M = fmaxf(m, m2);
        s = s * __expf(m - M) + s2 * __expf(m2 - M);
        m = M;
    }
    __shared__ float sm[4], ss[4];
    if ((tid & 31) == 0) { sm[tid >> 5] = m; ss[tid >> 5] = s; }
    __syncthreads();
    float M = fmaxf(fmaxf(sm[0], sm[1]), fmaxf(sm[2], sm[3]));
    float S_ = ss[0] * __expf(sm[0] - M) + ss[1] * __expf(sm[1] - M)
             + ss[2] * __expf(sm[2] - M) + ss[3] * __expf(sm[3] - M);
    const float rv = 1.0f / S_;

    for (int j = tid; j < TT / 4; j += 128) {
        const float4 v = p[j];
        const float f0 = __expf(v.x - M) * rv, f1 = __expf(v.y - M) * rv;
        const float f2 = __expf(v.z - M) * rv, f3 = __expf(v.w - M) * rv;
        __half2 l0, h0 = split_hi(f0, f1, l0);
        __half2 l1, h1 = split_hi(f2, f3, l1);
        __half2* ph = reinterpret_cast<__half2*>(oh + row * (long)TTP + j * 4);
        __half2* pl = reinterpret_cast<__half2*>(ol + row * (long)TTP + j * 4);
        ph[0] = h0; ph[1] = h1;
        pl[0] = l0; pl[1] = l1;
    }
}

// ---------------------------------------------------------------------------
extern "C" void kernel_launch(void* const* d_in, const int* in_sizes, int n_in,
                              void* d_out, int out_size)
{
    const float* X  = (const float*)d_in[0];
    const float* H  = (const float*)d_in[1];
    const float* W1 = (const float*)d_in[2];
    const float* W2 = (const float*)d_in[3];
    float* out = (float*)d_out;

    float* S;
    cudaGetSymbolAddress((void**)&S, g_S);
    __half *W2h, *W2l, *XTh, *XTl, *Hh, *Hl, *HTh, *HTl, *W1Th, *W1Tl;
    __half *M1h, *M1l, *Gh, *Gl, *Ph, *Pl;
    cudaGetSymbolAddress((void**)&W2h, g_W2h);   cudaGetSymbolAddress((void**)&W2l, g_W2l);
    cudaGetSymbolAddress((void**)&XTh, g_XTh);   cudaGetSymbolAddress((void**)&XTl, g_XTl);
    cudaGetSymbolAddress((void**)&Hh,  g_Hh);    cudaGetSymbolAddress((void**)&Hl,  g_Hl);
    cudaGetSymbolAddress((void**)&HTh, g_HTh);   cudaGetSymbolAddress((void**)&HTl, g_HTl);
    cudaGetSymbolAddress((void**)&W1Th, g_W1Th); cudaGetSymbolAddress((void**)&W1Tl, g_W1Tl);
    cudaGetSymbolAddress((void**)&M1h, g_M1h);   cudaGetSymbolAddress((void**)&M1l, g_M1l);
    cudaGetSymbolAddress((void**)&Gh,  g_Gh);    cudaGetSymbolAddress((void**)&Gl,  g_Gl);
    cudaGetSymbolAddress((void**)&Ph,  g_Ph);    cudaGetSymbolAddress((void**)&Pl,  g_Pl);

    cudaFuncSetAttribute(gemm_h3<0>, cudaFuncAttributeMaxDynamicSharedMemorySize, SMEM_BYTES);
    cudaFuncSetAttribute(gemm_h3<1>, cudaFuncAttributeMaxDynamicSharedMemorySize, SMEM_BYTES);
    cudaFuncSetAttribute(gemm_h3<2>, cudaFuncAttributeMaxDynamicSharedMemorySize, SMEM_BYTES);

    const float SCALE = (float)(1.0 / (sqrt((double)XD) * sqrt((double)HD)));

    // conversions
    {
        const long f = (long)CN * (TT / 4);
        split_rows<<<(unsigned)((f + 255) / 256), 256>>>(W2, W2h, W2l, CN, TT, TTP);
    }
    split_transpose<<<dim3(XD / 32, (TT + 31) / 32, BB), dim3(32, 8)>>>(
        X, XTh, XTl, TT, XD, TTP, (long)TT * XD, (long)XD * TTP);
    conv_H<<<dim3(HD / 32, (TT + 31) / 32, BB), dim3(32, 8)>>>(H, Hh, Hl, HTh, HTl);
    split_transpose<<<dim3(HD / 32, (XD + 31) / 32, 1), dim3(32, 8)>>>(
        W1, W1Th, W1Tl, XD, HD, XD, 0L, 0L);

    // K1 (merged over batch): M1[(b,c,x)] = sum_t W2[c,t] * XT[(b,x),t]
    //   M=CN, N=B*XD=6144, K=TT; scatter-out fp16 [b][c][x]
    gemm_h3<2><<<dim3(48, 3, 1), 256, SMEM_BYTES>>>(
        W2h, W2l, XTh, XTl, nullptr, M1h, M1l,
        CN, BB * XD, TT, TTP, TTP, 0,
        0L, 0L, (long)CN * XD, 1.0f);

    // K2 (merged): G[(b,c)][h] = SCALE * sum_x M1[(b,c),x] * W1T[h,x]
    //   M=B*CN=22080, N=HD, K=XD; out fp16 [(b,c)][h]
    gemm_h3<1><<<dim3(2, (BB * CN + 127) / 128, 1), 256, SMEM_BYTES>>>(
        M1h, M1l, W1Th, W1Tl, nullptr, Gh, Gl,
        BB * CN, HD, XD, XD, XD, HD,
        0L, 0L, 0L, SCALE);

    // K3 (batched): S[b] = G[b] @ H[b]^T   [CN,TT], K=HD; out fp32
    gemm_h3<0><<<dim3(11, 3, BB), 256, SMEM_BYTES>>>(
        Gh, Gl, Hh, Hl, S, nullptr, nullptr,
        CN, TT, HD, HD, HD, TT,
        (long)CN * HD, (long)TT * HD, (long)CN * TT, 1.0f);

    // K4: fused softmax stats + P split
    softmax_fused<<<BB * CN, 128>>>(S, Ph, Pl);

    // K5 (batched): out[b] = P[b] @ H[b]   [CN,HD], K=TT; out fp32
    gemm_h3<0><<<dim3(2, 3, BB), 256, SMEM_BYTES>>>(
        Ph, Pl, HTh, HTl, out, nullptr, nullptr,
        CN, HD, TT, TTP, TTP, HD,
        (long)CN * TTP, (long)HD * TTP, (long)CN * HD, 1.0f);
}